// round 10
// baseline (speedup 1.0000x reference)
#include <cuda_runtime.h>
#include <math.h>

#define N_NODES  50000
#define N_EDGES  800000
#define N_GRAPHS 50
#define FEAT     256

// ---------------- scratch (static device globals: no allocations) ----------
__device__ float g_bufA[(size_t)N_NODES * FEAT];   // GEMM output h (both layers)
__device__ float g_bufB[(size_t)N_NODES * FEAT];   // aggregated/relu output (both layers)
__device__ float g_asrc[N_NODES * 4];
__device__ float g_adst[N_NODES * 4];
__device__ int   g_rowptr[N_NODES + 1];
__device__ int   g_cursor[N_NODES];
__device__ int   g_esrc[N_EDGES];
__device__ float g_pool[N_GRAPHS * FEAT];
__device__ float g_cnt[N_GRAPHS];

// ---------------- zero the per-call accumulators ----------------
__global__ void k_zero() {
    int i = blockIdx.x * blockDim.x + threadIdx.x;
    if (i <= N_NODES) g_rowptr[i] = 0;
    if (i < N_GRAPHS * FEAT) g_pool[i] = 0.f;
    if (i < N_GRAPHS) g_cnt[i] = 0.f;
}

// ---------------- CSR build: degree count ----------------
__global__ void k_deg(const int* __restrict__ dst) {
    int e = blockIdx.x * blockDim.x + threadIdx.x;
    if (e < N_EDGES) atomicAdd(&g_rowptr[dst[e] + 1], 1);
}

// ---------------- single-block inclusive scan over rowptr ----------------
__global__ void k_scan() {
    const int n = N_NODES + 1;
    const int T = 1024;
    __shared__ int sums[T];
    int t = threadIdx.x;
    const int CH = (n + T - 1) / T;
    int beg = t * CH;
    int end = min(beg + CH, n);
    int s = 0;
    for (int i = beg; i < end; i++) { s += g_rowptr[i]; g_rowptr[i] = s; }
    sums[t] = s;
    __syncthreads();
    for (int off = 1; off < T; off <<= 1) {
        int v = sums[t];
        int u = (t >= off) ? sums[t - off] : 0;
        __syncthreads();
        sums[t] = v + u;
        __syncthreads();
    }
    int add = (t > 0) ? sums[t - 1] : 0;
    if (add) {
        for (int i = beg; i < end; i++) g_rowptr[i] += add;
    }
}

__global__ void k_cursor() {
    int i = blockIdx.x * blockDim.x + threadIdx.x;
    if (i < N_NODES) g_cursor[i] = g_rowptr[i];
}

__global__ void k_scatter(const int* __restrict__ src, const int* __restrict__ dst) {
    int e = blockIdx.x * blockDim.x + threadIdx.x;
    if (e < N_EDGES) {
        int pos = atomicAdd(&g_cursor[dst[e]], 1);
        g_esrc[pos] = src[e];
    }
}

// ---------------- SGEMM: C[M,256] = A[M,256] @ B[256,256] ----------------
// mode 0: A = Aext (external input), mode 1: A = g_bufB. C is always g_bufA.
__global__ __launch_bounds__(256) void k_sgemm(const float* __restrict__ Aext,
                                               const float* __restrict__ B,
                                               int M, int mode) {
    constexpr int BM = 128, BN = 128, BK = 16;
    const int K = 256, N = 256;
    __shared__ float As[BK][BM];
    __shared__ float Bs[BK][BN];
    const float* A = (mode == 0) ? Aext : g_bufB;
    float* C = g_bufA;

    int bm = blockIdx.x * BM;
    int bn = blockIdx.y * BN;
    int tid = threadIdx.x;
    int tx = tid % 16, ty = tid / 16;
    float acc[8][8];
#pragma unroll
    for (int i = 0; i < 8; i++)
#pragma unroll
        for (int j = 0; j < 8; j++) acc[i][j] = 0.f;

    for (int k0 = 0; k0 < K; k0 += BK) {
#pragma unroll
        for (int i = 0; i < 2; i++) {
            int idx = tid + i * 256;          // 0..511 (512 float4 loads)
            int r = idx >> 2;                 // 0..127
            int kc = (idx & 3) * 4;           // 0,4,8,12
            int row = bm + r;
            float4 v = make_float4(0.f, 0.f, 0.f, 0.f);
            if (row < M) v = *(const float4*)(A + (size_t)row * K + k0 + kc);
            As[kc + 0][r] = v.x; As[kc + 1][r] = v.y;
            As[kc + 2][r] = v.z; As[kc + 3][r] = v.w;
        }
#pragma unroll
        for (int i = 0; i < 2; i++) {
            int idx = tid + i * 256;
            int kr = idx >> 5;                // 0..15
            int c = (idx & 31) * 4;           // 0..124
            *(float4*)(&Bs[kr][c]) = *(const float4*)(B + (size_t)(k0 + kr) * N + bn + c);
        }
        __syncthreads();
#pragma unroll
        for (int k = 0; k < BK; k++) {
            float4 a0 = *(const float4*)&As[k][ty * 8];
            float4 a1 = *(const float4*)&As[k][ty * 8 + 4];
            float4 b0 = *(const float4*)&Bs[k][tx * 8];
            float4 b1 = *(const float4*)&Bs[k][tx * 8 + 4];
            float ra[8] = {a0.x, a0.y, a0.z, a0.w, a1.x, a1.y, a1.z, a1.w};
            float rb[8] = {b0.x, b0.y, b0.z, b0.w, b1.x, b1.y, b1.z, b1.w};
#pragma unroll
            for (int i = 0; i < 8; i++)
#pragma unroll
                for (int j = 0; j < 8; j++)
                    acc[i][j] = fmaf(ra[i], rb[j], acc[i][j]);
        }
        __syncthreads();
    }
#pragma unroll
    for (int i = 0; i < 8; i++) {
        int row = bm + ty * 8 + i;
        if (row < M) {
            float4* cp = (float4*)(C + (size_t)row * N + bn + tx * 8);
            cp[0] = make_float4(acc[i][0], acc[i][1], acc[i][2], acc[i][3]);
            cp[1] = make_float4(acc[i][4], acc[i][5], acc[i][6], acc[i][7]);
        }
    }
}

// ---------------- per-node attention logits: warp per node ----------------
template <int H>
__global__ void k_att(const float* __restrict__ att_src, const float* __restrict__ att_dst) {
    int node = (blockIdx.x * blockDim.x + threadIdx.x) >> 5;
    if (node >= N_NODES) return;
    int lane = threadIdx.x & 31;
    const float4* hp = (const float4*)(g_bufA + (size_t)node * FEAT + lane * 8);
    float4 h0 = hp[0], h1 = hp[1];
    const float4* sp = (const float4*)(att_src + lane * 8);
    float4 s0 = sp[0], s1 = sp[1];
    const float4* dp = (const float4*)(att_dst + lane * 8);
    float4 d0 = dp[0], d1 = dp[1];
    float ps = h0.x * s0.x + h0.y * s0.y + h0.z * s0.z + h0.w * s0.w +
               h1.x * s1.x + h1.y * s1.y + h1.z * s1.z + h1.w * s1.w;
    float pd = h0.x * d0.x + h0.y * d0.y + h0.z * d0.z + h0.w * d0.w +
               h1.x * d1.x + h1.y * d1.y + h1.z * d1.z + h1.w * d1.w;
    constexpr int G = (FEAT / H) / 8;  // lanes per head (8 for H=4, 32 for H=1)
#pragma unroll
    for (int off = G >> 1; off > 0; off >>= 1) {
        ps += __shfl_down_sync(0xffffffffu, ps, off, G);
        pd += __shfl_down_sync(0xffffffffu, pd, off, G);
    }
    if ((lane & (G - 1)) == 0) {
        int head = lane / G;
        g_asrc[node * H + head] = ps;
        g_adst[node * H + head] = pd;
    }
}

// ---------------- CSR aggregation with online softmax: warp per dst node --
template <int H>
__global__ void k_agg(const float* __restrict__ bias) {
    int node = (blockIdx.x * blockDim.x + threadIdx.x) >> 5;
    if (node >= N_NODES) return;
    int lane = threadIdx.x & 31;
    constexpr int G = (FEAT / H) / 8;  // lanes per head
    int head = lane / G;
    float ad = g_adst[node * H + head];
    float m = -INFINITY, s = 0.f;
    float acc[8] = {0.f, 0.f, 0.f, 0.f, 0.f, 0.f, 0.f, 0.f};
    int beg = g_rowptr[node], end = g_rowptr[node + 1];
    for (int e = beg; e < end; e++) {
        int src = g_esrc[e];
        const float4* hp = (const float4*)(g_bufA + (size_t)src * FEAT + lane * 8);
        float4 v0 = hp[0], v1 = hp[1];
        float av = g_asrc[src * H + head] + ad;
        float ee = (av > 0.f) ? av : 0.2f * av;      // leaky_relu(0.2)
        float nm = fmaxf(m, ee);
        float scale = __expf(m - nm);                // exp(-inf)=0 on first edge
        float w = __expf(ee - nm);
        m = nm;
        s = s * scale + w;
        acc[0] = acc[0] * scale + w * v0.x;
        acc[1] = acc[1] * scale + w * v0.y;
        acc[2] = acc[2] * scale + w * v0.z;
        acc[3] = acc[3] * scale + w * v0.w;
        acc[4] = acc[4] * scale + w * v1.x;
        acc[5] = acc[5] * scale + w * v1.y;
        acc[6] = acc[6] * scale + w * v1.z;
        acc[7] = acc[7] * scale + w * v1.w;
    }
    float inv = (s > 0.f) ? 1.f / s : 0.f;           // empty segment -> 0 + bias
    const float4* bp = (const float4*)(bias + lane * 8);
    float4 b0 = bp[0], b1 = bp[1];
    float4 o0 = make_float4(fmaxf(acc[0] * inv + b0.x, 0.f),
                            fmaxf(acc[1] * inv + b0.y, 0.f),
                            fmaxf(acc[2] * inv + b0.z, 0.f),
                            fmaxf(acc[3] * inv + b0.w, 0.f));
    float4 o1 = make_float4(fmaxf(acc[4] * inv + b1.x, 0.f),
                            fmaxf(acc[5] * inv + b1.y, 0.f),
                            fmaxf(acc[6] * inv + b1.z, 0.f),
                            fmaxf(acc[7] * inv + b1.w, 0.f));
    float4* op = (float4*)(g_bufB + (size_t)node * FEAT + lane * 8);
    op[0] = o0;
    op[1] = o1;
}

// ---------------- global mean pool (batch is sorted): run-length flush ----
__global__ void k_pool(const int* __restrict__ batch) {
    constexpr int ROWS = 128;
    __shared__ int sb[ROWS];
    int n0 = blockIdx.x * ROWS;
    int tid = threadIdx.x;  // 256 threads = one per feature column
    for (int i = tid; i < ROWS; i += 256) {
        int n = n0 + i;
        sb[i] = (n < N_NODES) ? batch[n] : -1;
    }
    __syncthreads();
    float acc = 0.f;
    int cur = sb[0];
    for (int i = 0; i < ROWS; i++) {
        int g = sb[i];
        if (g < 0) break;
        if (g != cur) {
            atomicAdd(&g_pool[cur * FEAT + tid], acc);
            acc = 0.f;
            cur = g;
        }
        acc += g_bufB[(size_t)(n0 + i) * FEAT + tid];
    }
    if (cur >= 0) atomicAdd(&g_pool[cur * FEAT + tid], acc);
}

__global__ void k_cnt(const int* __restrict__ batch) {
    int n = blockIdx.x * blockDim.x + threadIdx.x;
    if (n < N_NODES) atomicAdd(&g_cnt[batch[n]], 1.f);
}

// ---------------- final FC: out[50,256] = relu(mean_pool @ Wfc + bfc) -----
__global__ void k_fc(const float* __restrict__ Wfc, const float* __restrict__ bfc,
                     float* __restrict__ out) {
    int g = blockIdx.x;
    int tid = threadIdx.x;  // 256
    __shared__ float p[FEAT];
    float inv = 1.f / fmaxf(g_cnt[g], 1.f);
    p[tid] = g_pool[g * FEAT + tid] * inv;
    __syncthreads();
    float s = bfc[tid];
#pragma unroll 8
    for (int k = 0; k < FEAT; k++) s = fmaf(p[k], Wfc[k * FEAT + tid], s);
    out[g * FEAT + tid] = fmaxf(s, 0.f);
}

// ---------------- launcher -------------------------------------------------
extern "C" void kernel_launch(void* const* d_in, const int* in_sizes, int n_in,
                              void* d_out, int out_size) {
    const float* x        = (const float*)d_in[0];
    const int*   edges    = (const int*)d_in[1];
    const int*   batch    = (const int*)d_in[2];
    const float* W1       = (const float*)d_in[3];
    const float* att_src1 = (const float*)d_in[4];
    const float* att_dst1 = (const float*)d_in[5];
    const float* b1       = (const float*)d_in[6];
    const float* W2       = (const float*)d_in[7];
    const float* att_src2 = (const float*)d_in[8];
    const float* att_dst2 = (const float*)d_in[9];
    const float* b2       = (const float*)d_in[10];
    const float* Wfc      = (const float*)d_in[11];
    const float* bfc      = (const float*)d_in[12];
    float* out = (float*)d_out;

    const int* srcp = edges;             // edge_index[0]
    const int* dstp = edges + N_EDGES;   // edge_index[1]

    // zero accumulators + build CSR by destination
    k_zero<<<(N_NODES + 256) / 256, 256>>>();
    k_deg<<<(N_EDGES + 255) / 256, 256>>>(dstp);
    k_scan<<<1, 1024>>>();
    k_cursor<<<(N_NODES + 255) / 256, 256>>>();
    k_scatter<<<(N_EDGES + 255) / 256, 256>>>(srcp, dstp);

    dim3 ggrid((N_NODES + 127) / 128, FEAT / 128);
    int att_blocks = (N_NODES * 32 + 255) / 256;
    int agg_blocks = (N_NODES + 7) / 8;

    // layer 1 (H=4, C=64)
    k_sgemm<<<ggrid, 256>>>(x, W1, N_NODES, 0);
    k_att<4><<<att_blocks, 256>>>(att_src1, att_dst1);
    k_agg<4><<<agg_blocks, 256>>>(b1);

    // layer 2 (H=1, C=256)
    k_sgemm<<<ggrid, 256>>>(nullptr, W2, N_NODES, 1);
    k_att<1><<<att_blocks, 256>>>(att_src2, att_dst2);
    k_agg<1><<<agg_blocks, 256>>>(b2);

    // pool + FC head
    k_pool<<<(N_NODES + 127) / 128, 256>>>(batch);
    k_cnt<<<(N_NODES + 255) / 256, 256>>>(batch);
    k_fc<<<N_GRAPHS, 256>>>(Wfc, bfc, out);
}